// round 9
// baseline (speedup 1.0000x reference)
#include <cuda_runtime.h>
#include <math.h>

#define N_NODES 50000
#define F 256
#define HEADS 8
#define E0_MAX 800000

// ---------------- scratch (static device globals; no allocation) ----------------
__device__ float g_h[N_NODES * F];            // x @ W  (51.2 MB)
__device__ float g_asrc[N_NODES * HEADS];
__device__ float g_adst[N_NODES * HEADS];
__device__ int   g_deg[N_NODES];
__device__ int   g_off[N_NODES];
__device__ int   g_pos[N_NODES];
__device__ int   g_srcs[E0_MAX];

__device__ __forceinline__ unsigned f2tf32(float f) {
    unsigned r;
    asm("cvt.rna.tf32.f32 %0, %1;" : "=r"(r) : "f"(f));
    return r;
}

// ---------------- init: zero degree counters ----------------
__global__ void k_init(int N) {
    int i = blockIdx.x * blockDim.x + threadIdx.x;
    if (i < N) g_deg[i] = 0;
}

// ---------------- CSR build: count, scan, fill ----------------
__global__ void k_count(const int* __restrict__ ei, int E0) {
    int e = blockIdx.x * blockDim.x + threadIdx.x;
    if (e < E0) atomicAdd(&g_deg[ei[E0 + e]], 1);
}

__global__ __launch_bounds__(1024) void k_scan(int N) {
    __shared__ int partials[1024];
    int tid = threadIdx.x;
    int chunk = (N + 1023) >> 10;
    int beg = tid * chunk;
    int end = min(beg + chunk, N);
    int s = 0;
    for (int i = beg; i < end; i++) s += g_deg[i];
    partials[tid] = s;
    __syncthreads();
    for (int off = 1; off < 1024; off <<= 1) {
        int v = (tid >= off) ? partials[tid - off] : 0;
        __syncthreads();
        partials[tid] += v;
        __syncthreads();
    }
    int run = (tid == 0) ? 0 : partials[tid - 1];
    for (int i = beg; i < end; i++) {
        g_off[i] = run;
        g_pos[i] = run;
        run += g_deg[i];
    }
}

__global__ void k_fill(const int* __restrict__ ei, int E0) {
    int e = blockIdx.x * blockDim.x + threadIdx.x;
    if (e >= E0) return;
    int s = ei[e], d = ei[E0 + e];
    int idx = atomicAdd(&g_pos[d], 1);
    g_srcs[idx] = s;
}

// ---------------- tf32 GEMM + fused attention-logit epilogue ----------------
#define ASTR 36
#define BSTR 136
#define A_ELEMS (128 * ASTR)
#define B_ELEMS (32 * BSTR)
#define ATT_OFF (2 * A_ELEMS + 2 * B_ELEMS)

__global__ __launch_bounds__(256, 2) void k_gemm(
    const float* __restrict__ A, const float* __restrict__ B, float* __restrict__ Cm,
    const float* __restrict__ attSrc, const float* __restrict__ attDst, int M)
{
    extern __shared__ float smem[];
    const int bm = blockIdx.y * 128;
    const int bn = blockIdx.x * 128;
    const int tid = threadIdx.x;
    const int wid = tid >> 5, lane = tid & 31;
    const int wm = (wid & 3) * 32;
    const int wn = (wid >> 2) * 64;
    const int g = lane >> 2, t = lane & 3;

    const int ar = tid >> 3, ac = (tid & 7) * 4;
    const int br = tid >> 6, bc = (tid & 63) * 2;

    if (tid < 128)      smem[ATT_OFF + tid] = attSrc[bn + tid];
    else                smem[ATT_OFF + 128 + (tid - 128)] = attDst[bn + tid - 128];

    float acc[2][8][4];
    #pragma unroll
    for (int mi = 0; mi < 2; mi++)
        #pragma unroll
        for (int ni = 0; ni < 8; ni++)
            #pragma unroll
            for (int q = 0; q < 4; q++) acc[mi][ni][q] = 0.f;

    float4 ra[4];
    float2 rb[8];

    auto ldg_tile = [&](int k0) {
        #pragma unroll
        for (int p = 0; p < 4; p++) {
            int r = ar + p * 32;
            ra[p] = make_float4(0.f, 0.f, 0.f, 0.f);
            if (bm + r < M) ra[p] = *(const float4*)&A[(long)(bm + r) * F + k0 + ac];
        }
        #pragma unroll
        for (int p = 0; p < 8; p++) {
            int r = br + p * 4;
            rb[p] = *(const float2*)&B[(long)(k0 + r) * F + bn + bc];
        }
    };
    auto sts_tile = [&](int st) {
        float* As = smem + st * A_ELEMS;
        float* Bs = smem + 2 * A_ELEMS + st * B_ELEMS;
        #pragma unroll
        for (int p = 0; p < 4; p++) {
            float4 w;
            w.x = __uint_as_float(f2tf32(ra[p].x)); w.y = __uint_as_float(f2tf32(ra[p].y));
            w.z = __uint_as_float(f2tf32(ra[p].z)); w.w = __uint_as_float(f2tf32(ra[p].w));
            *(float4*)&As[(ar + p * 32) * ASTR + ac] = w;
        }
        #pragma unroll
        for (int p = 0; p < 8; p++) {
            float2 w;
            w.x = __uint_as_float(f2tf32(rb[p].x)); w.y = __uint_as_float(f2tf32(rb[p].y));
            *(float2*)&Bs[(br + p * 4) * BSTR + bc] = w;
        }
    };
    auto compute = [&](int st) {
        float* As = smem + st * A_ELEMS;
        float* Bs = smem + 2 * A_ELEMS + st * B_ELEMS;
        #pragma unroll
        for (int kk = 0; kk < 4; kk++) {
            const int k = kk * 8;
            unsigned a[2][4], b[8][2];
            #pragma unroll
            for (int mi = 0; mi < 2; mi++) {
                int rb0 = wm + mi * 16;
                a[mi][0] = __float_as_uint(As[(rb0 + g) * ASTR + k + t]);
                a[mi][1] = __float_as_uint(As[(rb0 + g + 8) * ASTR + k + t]);
                a[mi][2] = __float_as_uint(As[(rb0 + g) * ASTR + k + t + 4]);
                a[mi][3] = __float_as_uint(As[(rb0 + g + 8) * ASTR + k + t + 4]);
            }
            #pragma unroll
            for (int ni = 0; ni < 8; ni++) {
                int col = wn + ni * 8 + g;
                b[ni][0] = __float_as_uint(Bs[(k + t) * BSTR + col]);
                b[ni][1] = __float_as_uint(Bs[(k + t + 4) * BSTR + col]);
            }
            #pragma unroll
            for (int mi = 0; mi < 2; mi++)
                #pragma unroll
                for (int ni = 0; ni < 8; ni++) {
                    asm volatile(
                        "mma.sync.aligned.m16n8k8.row.col.f32.tf32.tf32.f32 "
                        "{%0,%1,%2,%3}, {%4,%5,%6,%7}, {%8,%9}, {%0,%1,%2,%3};"
                        : "+f"(acc[mi][ni][0]), "+f"(acc[mi][ni][1]),
                          "+f"(acc[mi][ni][2]), "+f"(acc[mi][ni][3])
                        : "r"(a[mi][0]), "r"(a[mi][1]), "r"(a[mi][2]), "r"(a[mi][3]),
                          "r"(b[ni][0]), "r"(b[ni][1]));
                }
        }
    };

    ldg_tile(0);
    sts_tile(0);
    __syncthreads();
    #pragma unroll
    for (int kt = 1; kt < 8; kt++) {
        ldg_tile(kt * 32);
        compute((kt - 1) & 1);
        sts_tile(kt & 1);
        __syncthreads();
    }
    compute(1);

    #pragma unroll
    for (int mi = 0; mi < 2; mi++) {
        #pragma unroll
        for (int ni = 0; ni < 8; ni++) {
            int col = bn + wn + ni * 8 + t * 2;
            int r0 = bm + wm + mi * 16 + g;
            int r1 = r0 + 8;
            if (r0 < M) *(float2*)&Cm[(long)r0 * F + col] = make_float2(acc[mi][ni][0], acc[mi][ni][1]);
            if (r1 < M) *(float2*)&Cm[(long)r1 * F + col] = make_float2(acc[mi][ni][2], acc[mi][ni][3]);
        }
    }

    const float* attS = smem + ATT_OFF;
    const float* attD = smem + ATT_OFF + 128;
    const int hbA = (bn + wn) >> 5;
    #pragma unroll
    for (int mi = 0; mi < 2; mi++) {
        #pragma unroll
        for (int rr = 0; rr < 2; rr++) {
            int row = bm + wm + mi * 16 + g + rr * 8;
            float sA = 0.f, dA = 0.f, sB = 0.f, dB = 0.f;
            #pragma unroll
            for (int ni = 0; ni < 8; ni++) {
                #pragma unroll
                for (int q = 0; q < 2; q++) {
                    int col = wn + ni * 8 + t * 2 + q;
                    float a = acc[mi][ni][rr * 2 + q];
                    if (ni < 4) { sA = fmaf(a, attS[col], sA); dA = fmaf(a, attD[col], dA); }
                    else        { sB = fmaf(a, attS[col], sB); dB = fmaf(a, attD[col], dB); }
                }
            }
            sA += __shfl_xor_sync(0xffffffffu, sA, 1); sA += __shfl_xor_sync(0xffffffffu, sA, 2);
            dA += __shfl_xor_sync(0xffffffffu, dA, 1); dA += __shfl_xor_sync(0xffffffffu, dA, 2);
            sB += __shfl_xor_sync(0xffffffffu, sB, 1); sB += __shfl_xor_sync(0xffffffffu, sB, 2);
            dB += __shfl_xor_sync(0xffffffffu, dB, 1); dB += __shfl_xor_sync(0xffffffffu, dB, 2);
            if (t == 0 && row < M) {
                g_asrc[row * 8 + hbA]     = sA;
                g_adst[row * 8 + hbA]     = dA;
                g_asrc[row * 8 + hbA + 1] = sB;
                g_adst[row * 8 + hbA + 1] = dB;
            }
        }
    }
}

// ---------------- fused aggregate: TWO warps per dst node, batched gathers ---
// warp w handles node n = w>>1, half = w&1 (channels [half*128, half*128+128),
// heads [half*4, half*4+4)). lane owns float4 at half*128 + lane*4, head lane>>3.
// Edges processed in batches of 4: all gathers issued before consumption (MLP=4).
__global__ __launch_bounds__(256) void k_agg(const float* __restrict__ bias,
                                             float* __restrict__ out, int N) {
    int w = (blockIdx.x * blockDim.x + threadIdx.x) >> 5;
    int lane = threadIdx.x & 31;
    int n = w >> 1, half = w & 1;
    if (n >= N) return;
    const int hsel = lane >> 3;            // head within this half: 0..3
    const int hb = half * 4;               // global head base
    const int voff = half * 32 + lane;     // float4 index within a 256-float row
    const float4* H = (const float4*)g_h;

    float adst_l = 0.f, aself_l = 0.f;
    if (lane < 4) {
        adst_l  = g_adst[n * 8 + hb + lane];
        aself_l = g_asrc[n * 8 + hb + lane];
    }
    // self loop
    float a0 = aself_l + adst_l;
    float ex_l = expf(a0 > 0.f ? a0 : 0.2f * a0);
    float e0 = __shfl_sync(0xffffffffu, ex_l, hsel);
    float4 v = H[(long)n * 64 + voff];
    float den = e0;
    float4 acc = make_float4(e0 * v.x, e0 * v.y, e0 * v.z, e0 * v.w);

    const int deg  = g_deg[n];
    const int base = g_off[n];
    for (int i = 0; i < deg; i += 4) {
        const int m = deg - i;
        int s0 = g_srcs[base + i];
        int s1 = g_srcs[base + i + (m > 1 ? 1 : 0)];
        int s2 = g_srcs[base + i + (m > 2 ? 2 : 0)];
        int s3 = g_srcs[base + i + (m > 3 ? 3 : 0)];
        // issue all gathers up front (4-deep MLP)
        float4 v0 = H[(long)s0 * 64 + voff];
        float4 v1 = H[(long)s1 * 64 + voff];
        float4 v2 = H[(long)s2 * 64 + voff];
        float4 v3 = H[(long)s3 * 64 + voff];
        float al0 = 0.f, al1 = 0.f, al2 = 0.f, al3 = 0.f;
        if (lane < 4) {
            al0 = g_asrc[s0 * 8 + hb + lane];
            al1 = g_asrc[s1 * 8 + hb + lane];
            al2 = g_asrc[s2 * 8 + hb + lane];
            al3 = g_asrc[s3 * 8 + hb + lane];
        }
        {
            float aa = al0 + adst_l;
            float el = expf(aa > 0.f ? aa : 0.2f * aa);
            float e = __shfl_sync(0xffffffffu, el, hsel);
            den += e;
            acc.x = fmaf(e, v0.x, acc.x); acc.y = fmaf(e, v0.y, acc.y);
            acc.z = fmaf(e, v0.z, acc.z); acc.w = fmaf(e, v0.w, acc.w);
        }
        if (m > 1) {
            float aa = al1 + adst_l;
            float el = expf(aa > 0.f ? aa : 0.2f * aa);
            float e = __shfl_sync(0xffffffffu, el, hsel);
            den += e;
            acc.x = fmaf(e, v1.x, acc.x); acc.y = fmaf(e, v1.y, acc.y);
            acc.z = fmaf(e, v1.z, acc.z); acc.w = fmaf(e, v1.w, acc.w);
        }
        if (m > 2) {
            float aa = al2 + adst_l;
            float el = expf(aa > 0.f ? aa : 0.2f * aa);
            float e = __shfl_sync(0xffffffffu, el, hsel);
            den += e;
            acc.x = fmaf(e, v2.x, acc.x); acc.y = fmaf(e, v2.y, acc.y);
            acc.z = fmaf(e, v2.z, acc.z); acc.w = fmaf(e, v2.w, acc.w);
        }
        if (m > 3) {
            float aa = al3 + adst_l;
            float el = expf(aa > 0.f ? aa : 0.2f * aa);
            float e = __shfl_sync(0xffffffffu, el, hsel);
            den += e;
            acc.x = fmaf(e, v3.x, acc.x); acc.y = fmaf(e, v3.y, acc.y);
            acc.z = fmaf(e, v3.z, acc.z); acc.w = fmaf(e, v3.w, acc.w);
        }
    }

    float r = 1.0f / (den + 1e-16f);
    float4 b = ((const float4*)bias)[voff];
    float4 o;
    o.x = acc.x * r + b.x; o.y = acc.y * r + b.y;
    o.z = acc.z * r + b.z; o.w = acc.w * r + b.w;
    o.x = o.x > 0.f ? o.x : expm1f(o.x);
    o.y = o.y > 0.f ? o.y : expm1f(o.y);
    o.z = o.z > 0.f ? o.z : expm1f(o.z);
    o.w = o.w > 0.f ? o.w : expm1f(o.w);
    ((float4*)&out[(long)n * F])[voff] = o;
}

// ---------------- launch ----------------
extern "C" void kernel_launch(void* const* d_in, const int* in_sizes, int n_in,
                              void* d_out, int out_size) {
    const float* x    = (const float*)d_in[0];
    const int*   ei   = (const int*)d_in[1];
    const float* W    = (const float*)d_in[2];
    const float* asv  = (const float*)d_in[3];
    const float* adv  = (const float*)d_in[4];
    const float* bias = (const float*)d_in[5];
    float* out = (float*)d_out;

    const int N  = in_sizes[0] / F;          // 50000
    const int E0 = in_sizes[1] / 2;          // 800000

    float* h_ptr;    cudaGetSymbolAddress((void**)&h_ptr, g_h);

    const int smem_bytes = (ATT_OFF + 256) * (int)sizeof(float);
    cudaFuncSetAttribute(k_gemm, cudaFuncAttributeMaxDynamicSharedMemorySize, smem_bytes);

    k_init<<<(N + 255) / 256, 256>>>(N);                        // 0
    k_count<<<(E0 + 255) / 256, 256>>>(ei, E0);                 // 1
    k_scan<<<1, 1024>>>(N);                                     // 2
    {
        dim3 grid(F / 128, (N + 127) / 128);
        k_gemm<<<grid, 256, smem_bytes>>>(x, W, h_ptr, asv, adv, N);  // 3 (profiled)
    }
    k_fill<<<(E0 + 255) / 256, 256>>>(ei, E0);                  // 4
    {
        int warps = 2 * N;
        int blocks = (warps + 7) / 8;
        k_agg<<<blocks, 256>>>(bias, out, N);                   // 5
    }
}

// round 13
// speedup vs baseline: 1.5248x; 1.5248x over previous
#include <cuda_runtime.h>
#include <math.h>

#define N_NODES 50000
#define F 256
#define HEADS 8
#define E0_MAX 800000

// ---------------- scratch (static device globals; no allocation) ----------------
__device__ float g_h[N_NODES * F];            // x @ W  (51.2 MB)
__device__ float g_asrc[N_NODES * HEADS];
__device__ float g_adst[N_NODES * HEADS];
__device__ int   g_deg[N_NODES];
__device__ int   g_off[N_NODES];
__device__ int   g_pos[N_NODES];
__device__ int   g_srcs[E0_MAX];
__device__ int   g_blksum[256];
__device__ int   g_blkoff[256];

__device__ __forceinline__ unsigned f2tf32(float f) {
    unsigned r;
    asm("cvt.rna.tf32.f32 %0, %1;" : "=r"(r) : "f"(f));
    return r;
}

// ---------------- init: zero degree counters ----------------
__global__ void k_init(int N) {
    int i = blockIdx.x * blockDim.x + threadIdx.x;
    if (i < N) g_deg[i] = 0;
}

// ---------------- CSR build: count, hierarchical scan, fill ----------------
__global__ void k_count(const int* __restrict__ ei, int E0) {
    int e = blockIdx.x * blockDim.x + threadIdx.x;
    if (e < E0) atomicAdd(&g_deg[ei[E0 + e]], 1);
}

// per-block sums of g_deg (256 elems per block)
__global__ __launch_bounds__(256) void k_scanA(int N) {
    __shared__ int sh[256];
    int t = threadIdx.x;
    int i = blockIdx.x * 256 + t;
    sh[t] = (i < N) ? g_deg[i] : 0;
    __syncthreads();
    for (int off = 128; off > 0; off >>= 1) {
        if (t < off) sh[t] += sh[t + off];
        __syncthreads();
    }
    if (t == 0) g_blksum[blockIdx.x] = sh[0];
}

// exclusive scan of block sums (single tiny block)
__global__ __launch_bounds__(256) void k_scanB(int NB) {
    __shared__ int sh[256];
    int t = threadIdx.x;
    sh[t] = (t < NB) ? g_blksum[t] : 0;
    __syncthreads();
    for (int off = 1; off < 256; off <<= 1) {
        int v = (t >= off) ? sh[t - off] : 0;
        __syncthreads();
        sh[t] += v;
        __syncthreads();
    }
    if (t < NB) g_blkoff[t] = (t == 0) ? 0 : sh[t - 1];
}

// block-local exclusive scan + global offset -> g_off, g_pos
__global__ __launch_bounds__(256) void k_scanC(int N) {
    __shared__ int sh[256];
    int t = threadIdx.x;
    int i = blockIdx.x * 256 + t;
    int d = (i < N) ? g_deg[i] : 0;
    sh[t] = d;
    __syncthreads();
    for (int off = 1; off < 256; off <<= 1) {
        int v = (t >= off) ? sh[t - off] : 0;
        __syncthreads();
        sh[t] += v;
        __syncthreads();
    }
    if (i < N) {
        int ex = sh[t] - d + g_blkoff[blockIdx.x];   // exclusive
        g_off[i] = ex;
        g_pos[i] = ex;
    }
}

__global__ void k_fill(const int* __restrict__ ei, int E0) {
    int e = blockIdx.x * blockDim.x + threadIdx.x;
    if (e >= E0) return;
    int s = ei[e], d = ei[E0 + e];
    int idx = atomicAdd(&g_pos[d], 1);
    g_srcs[idx] = s;
}

// ---------------- tf32 GEMM + fused attention-logit epilogue ----------------
#define ASTR 36
#define BSTR 136
#define A_ELEMS (128 * ASTR)
#define B_ELEMS (32 * BSTR)
#define ATT_OFF (2 * A_ELEMS + 2 * B_ELEMS)

__global__ __launch_bounds__(256, 2) void k_gemm(
    const float* __restrict__ A, const float* __restrict__ B, float* __restrict__ Cm,
    const float* __restrict__ attSrc, const float* __restrict__ attDst, int M)
{
    extern __shared__ float smem[];
    const int bm = blockIdx.y * 128;
    const int bn = blockIdx.x * 128;
    const int tid = threadIdx.x;
    const int wid = tid >> 5, lane = tid & 31;
    const int wm = (wid & 3) * 32;
    const int wn = (wid >> 2) * 64;
    const int g = lane >> 2, t = lane & 3;

    const int ar = tid >> 3, ac = (tid & 7) * 4;
    const int br = tid >> 6, bc = (tid & 63) * 2;

    if (tid < 128)      smem[ATT_OFF + tid] = attSrc[bn + tid];
    else                smem[ATT_OFF + 128 + (tid - 128)] = attDst[bn + tid - 128];

    float acc[2][8][4];
    #pragma unroll
    for (int mi = 0; mi < 2; mi++)
        #pragma unroll
        for (int ni = 0; ni < 8; ni++)
            #pragma unroll
            for (int q = 0; q < 4; q++) acc[mi][ni][q] = 0.f;

    float4 ra[4];
    float2 rb[8];

    auto ldg_tile = [&](int k0) {
        #pragma unroll
        for (int p = 0; p < 4; p++) {
            int r = ar + p * 32;
            ra[p] = make_float4(0.f, 0.f, 0.f, 0.f);
            if (bm + r < M) ra[p] = *(const float4*)&A[(long)(bm + r) * F + k0 + ac];
        }
        #pragma unroll
        for (int p = 0; p < 8; p++) {
            int r = br + p * 4;
            rb[p] = *(const float2*)&B[(long)(k0 + r) * F + bn + bc];
        }
    };
    auto sts_tile = [&](int st) {
        float* As = smem + st * A_ELEMS;
        float* Bs = smem + 2 * A_ELEMS + st * B_ELEMS;
        #pragma unroll
        for (int p = 0; p < 4; p++) {
            float4 w;
            w.x = __uint_as_float(f2tf32(ra[p].x)); w.y = __uint_as_float(f2tf32(ra[p].y));
            w.z = __uint_as_float(f2tf32(ra[p].z)); w.w = __uint_as_float(f2tf32(ra[p].w));
            *(float4*)&As[(ar + p * 32) * ASTR + ac] = w;
        }
        #pragma unroll
        for (int p = 0; p < 8; p++) {
            float2 w;
            w.x = __uint_as_float(f2tf32(rb[p].x)); w.y = __uint_as_float(f2tf32(rb[p].y));
            *(float2*)&Bs[(br + p * 4) * BSTR + bc] = w;
        }
    };
    auto compute = [&](int st) {
        float* As = smem + st * A_ELEMS;
        float* Bs = smem + 2 * A_ELEMS + st * B_ELEMS;
        #pragma unroll
        for (int kk = 0; kk < 4; kk++) {
            const int k = kk * 8;
            unsigned a[2][4], b[8][2];
            #pragma unroll
            for (int mi = 0; mi < 2; mi++) {
                int rb0 = wm + mi * 16;
                a[mi][0] = __float_as_uint(As[(rb0 + g) * ASTR + k + t]);
                a[mi][1] = __float_as_uint(As[(rb0 + g + 8) * ASTR + k + t]);
                a[mi][2] = __float_as_uint(As[(rb0 + g) * ASTR + k + t + 4]);
                a[mi][3] = __float_as_uint(As[(rb0 + g + 8) * ASTR + k + t + 4]);
            }
            #pragma unroll
            for (int ni = 0; ni < 8; ni++) {
                int col = wn + ni * 8 + g;
                b[ni][0] = __float_as_uint(Bs[(k + t) * BSTR + col]);
                b[ni][1] = __float_as_uint(Bs[(k + t + 4) * BSTR + col]);
            }
            #pragma unroll
            for (int mi = 0; mi < 2; mi++)
                #pragma unroll
                for (int ni = 0; ni < 8; ni++) {
                    asm volatile(
                        "mma.sync.aligned.m16n8k8.row.col.f32.tf32.tf32.f32 "
                        "{%0,%1,%2,%3}, {%4,%5,%6,%7}, {%8,%9}, {%0,%1,%2,%3};"
                        : "+f"(acc[mi][ni][0]), "+f"(acc[mi][ni][1]),
                          "+f"(acc[mi][ni][2]), "+f"(acc[mi][ni][3])
                        : "r"(a[mi][0]), "r"(a[mi][1]), "r"(a[mi][2]), "r"(a[mi][3]),
                          "r"(b[ni][0]), "r"(b[ni][1]));
                }
        }
    };

    ldg_tile(0);
    sts_tile(0);
    __syncthreads();
    #pragma unroll
    for (int kt = 1; kt < 8; kt++) {
        ldg_tile(kt * 32);
        compute((kt - 1) & 1);
        sts_tile(kt & 1);
        __syncthreads();
    }
    compute(1);

    #pragma unroll
    for (int mi = 0; mi < 2; mi++) {
        #pragma unroll
        for (int ni = 0; ni < 8; ni++) {
            int col = bn + wn + ni * 8 + t * 2;
            int r0 = bm + wm + mi * 16 + g;
            int r1 = r0 + 8;
            if (r0 < M) *(float2*)&Cm[(long)r0 * F + col] = make_float2(acc[mi][ni][0], acc[mi][ni][1]);
            if (r1 < M) *(float2*)&Cm[(long)r1 * F + col] = make_float2(acc[mi][ni][2], acc[mi][ni][3]);
        }
    }

    const float* attS = smem + ATT_OFF;
    const float* attD = smem + ATT_OFF + 128;
    const int hbA = (bn + wn) >> 5;
    #pragma unroll
    for (int mi = 0; mi < 2; mi++) {
        #pragma unroll
        for (int rr = 0; rr < 2; rr++) {
            int row = bm + wm + mi * 16 + g + rr * 8;
            float sA = 0.f, dA = 0.f, sB = 0.f, dB = 0.f;
            #pragma unroll
            for (int ni = 0; ni < 8; ni++) {
                #pragma unroll
                for (int q = 0; q < 2; q++) {
                    int col = wn + ni * 8 + t * 2 + q;
                    float a = acc[mi][ni][rr * 2 + q];
                    if (ni < 4) { sA = fmaf(a, attS[col], sA); dA = fmaf(a, attD[col], dA); }
                    else        { sB = fmaf(a, attS[col], sB); dB = fmaf(a, attD[col], dB); }
                }
            }
            sA += __shfl_xor_sync(0xffffffffu, sA, 1); sA += __shfl_xor_sync(0xffffffffu, sA, 2);
            dA += __shfl_xor_sync(0xffffffffu, dA, 1); dA += __shfl_xor_sync(0xffffffffu, dA, 2);
            sB += __shfl_xor_sync(0xffffffffu, sB, 1); sB += __shfl_xor_sync(0xffffffffu, sB, 2);
            dB += __shfl_xor_sync(0xffffffffu, dB, 1); dB += __shfl_xor_sync(0xffffffffu, dB, 2);
            if (t == 0 && row < M) {
                g_asrc[row * 8 + hbA]     = sA;
                g_adst[row * 8 + hbA]     = dA;
                g_asrc[row * 8 + hbA + 1] = sB;
                g_adst[row * 8 + hbA + 1] = dB;
            }
        }
    }
}

// ---------------- fused aggregate: one WARP per dst node (R6 form, best) ----
__global__ __launch_bounds__(256) void k_agg(const float* __restrict__ bias,
                                             float* __restrict__ out, int N) {
    int n = (blockIdx.x * blockDim.x + threadIdx.x) >> 5;
    int lane = threadIdx.x & 31;
    if (n >= N) return;
    const int hsel = lane >> 3;

    float adst_l = 0.f, aself_l = 0.f;
    if (lane < 8) {
        adst_l  = g_adst[n * 8 + lane];
        aself_l = g_asrc[n * 8 + lane];
    }
    float a0 = aself_l + adst_l;
    float ex_l = expf(a0 > 0.f ? a0 : 0.2f * a0);
    float eA = __shfl_sync(0xffffffffu, ex_l, hsel);
    float eB = __shfl_sync(0xffffffffu, ex_l, 4 + hsel);

    const float4* hn = (const float4*)&g_h[(long)n * F];
    float4 vA = hn[lane], vB = hn[32 + lane];
    float denA = eA, denB = eB;
    float4 accA = make_float4(eA * vA.x, eA * vA.y, eA * vA.z, eA * vA.w);
    float4 accB = make_float4(eB * vB.x, eB * vB.y, eB * vB.z, eB * vB.w);

    int deg  = g_deg[n];
    int base = g_off[n];
    #pragma unroll 4
    for (int i = 0; i < deg; i++) {
        int s = g_srcs[base + i];
        float asl = (lane < 8) ? g_asrc[s * 8 + lane] : 0.f;
        float aa = asl + adst_l;
        float el = expf(aa > 0.f ? aa : 0.2f * aa);
        float e1 = __shfl_sync(0xffffffffu, el, hsel);
        float e2 = __shfl_sync(0xffffffffu, el, 4 + hsel);
        const float4* hs = (const float4*)&g_h[(long)s * F];
        float4 wA = hs[lane], wB = hs[32 + lane];
        accA.x = fmaf(e1, wA.x, accA.x); accA.y = fmaf(e1, wA.y, accA.y);
        accA.z = fmaf(e1, wA.z, accA.z); accA.w = fmaf(e1, wA.w, accA.w);
        accB.x = fmaf(e2, wB.x, accB.x); accB.y = fmaf(e2, wB.y, accB.y);
        accB.z = fmaf(e2, wB.z, accB.z); accB.w = fmaf(e2, wB.w, accB.w);
        denA += e1; denB += e2;
    }

    float rA = 1.0f / (denA + 1e-16f);
    float rB = 1.0f / (denB + 1e-16f);
    const float4* b4 = (const float4*)bias;
    float4 bA = b4[lane], bB = b4[32 + lane];
    float4 oA, oB;
    oA.x = accA.x * rA + bA.x; oA.y = accA.y * rA + bA.y;
    oA.z = accA.z * rA + bA.z; oA.w = accA.w * rA + bA.w;
    oB.x = accB.x * rB + bB.x; oB.y = accB.y * rB + bB.y;
    oB.z = accB.z * rB + bB.z; oB.w = accB.w * rB + bB.w;
    oA.x = oA.x > 0.f ? oA.x : expm1f(oA.x);
    oA.y = oA.y > 0.f ? oA.y : expm1f(oA.y);
    oA.z = oA.z > 0.f ? oA.z : expm1f(oA.z);
    oA.w = oA.w > 0.f ? oA.w : expm1f(oA.w);
    oB.x = oB.x > 0.f ? oB.x : expm1f(oB.x);
    oB.y = oB.y > 0.f ? oB.y : expm1f(oB.y);
    oB.z = oB.z > 0.f ? oB.z : expm1f(oB.z);
    oB.w = oB.w > 0.f ? oB.w : expm1f(oB.w);
    float4* o4 = (float4*)&out[(long)n * F];
    o4[lane]      = oA;
    o4[32 + lane] = oB;
}

// ---------------- launch ----------------
extern "C" void kernel_launch(void* const* d_in, const int* in_sizes, int n_in,
                              void* d_out, int out_size) {
    const float* x    = (const float*)d_in[0];
    const int*   ei   = (const int*)d_in[1];
    const float* W    = (const float*)d_in[2];
    const float* asv  = (const float*)d_in[3];
    const float* adv  = (const float*)d_in[4];
    const float* bias = (const float*)d_in[5];
    float* out = (float*)d_out;

    const int N  = in_sizes[0] / F;          // 50000
    const int E0 = in_sizes[1] / 2;          // 800000
    const int NB = (N + 255) / 256;          // 196

    float* h_ptr;    cudaGetSymbolAddress((void**)&h_ptr, g_h);

    // one-time infra (created OUTSIDE capture on the first/correctness call;
    // reused identically on every call — no device memory involved)
    static cudaStream_t s_side = nullptr;
    static cudaEvent_t ev_fork = nullptr, ev_join = nullptr;
    if (s_side == nullptr) {
        cudaStreamCreateWithFlags(&s_side, cudaStreamNonBlocking);
        cudaEventCreateWithFlags(&ev_fork, cudaEventDisableTiming);
        cudaEventCreateWithFlags(&ev_join, cudaEventDisableTiming);
    }

    const int smem_bytes = (ATT_OFF + 256) * (int)sizeof(float);
    cudaFuncSetAttribute(k_gemm, cudaFuncAttributeMaxDynamicSharedMemorySize, smem_bytes);

    // fork: CSR build on side stream, GEMM on main stream (independent)
    cudaEventRecord(ev_fork, 0);
    cudaStreamWaitEvent(s_side, ev_fork, 0);

    k_init <<<NB, 256, 0, s_side>>>(N);                          // 0
    k_count<<<(E0 + 255) / 256, 256, 0, s_side>>>(ei, E0);       // 1
    k_scanA<<<NB, 256, 0, s_side>>>(N);                          // 2
    {
        dim3 grid(F / 128, (N + 127) / 128);
        k_gemm<<<grid, 256, smem_bytes>>>(x, W, h_ptr, asv, adv, N);   // 3 (profiled)
    }
    k_scanB<<<1, 256, 0, s_side>>>(NB);                          // 4
    k_scanC<<<NB, 256, 0, s_side>>>(N);                          // 5
    k_fill <<<(E0 + 255) / 256, 256, 0, s_side>>>(ei, E0);       // 6

    // join: aggregation needs both branches
    cudaEventRecord(ev_join, s_side);
    cudaStreamWaitEvent(0, ev_join, 0);
    {
        int blocks = (N + 7) / 8;
        k_agg<<<blocks, 256>>>(bias, out, N);                    // 7
    }
}

// round 14
// speedup vs baseline: 1.6776x; 1.1002x over previous
#include <cuda_runtime.h>
#include <cuda_fp16.h>
#include <math.h>

#define N_NODES 50000
#define F 256
#define HEADS 8
#define E0_MAX 800000

// ---------------- scratch (static device globals; no allocation) ----------------
__device__ __half g_hh[N_NODES * F];          // x @ W in fp16  (25.6 MB)
__device__ float g_asrc[N_NODES * HEADS];
__device__ float g_adst[N_NODES * HEADS];
__device__ int   g_deg[N_NODES];
__device__ int   g_off[N_NODES];
__device__ int   g_pos[N_NODES];
__device__ int   g_srcs[E0_MAX];
__device__ int   g_blksum[256];
__device__ int   g_blkoff[256];

__device__ __forceinline__ unsigned f2tf32(float f) {
    unsigned r;
    asm("cvt.rna.tf32.f32 %0, %1;" : "=r"(r) : "f"(f));
    return r;
}

// ---------------- init: zero degree counters ----------------
__global__ void k_init(int N) {
    int i = blockIdx.x * blockDim.x + threadIdx.x;
    if (i < N) g_deg[i] = 0;
}

// ---------------- CSR build: count, hierarchical scan, fill ----------------
__global__ void k_count(const int* __restrict__ ei, int E0) {
    int e = blockIdx.x * blockDim.x + threadIdx.x;
    if (e < E0) atomicAdd(&g_deg[ei[E0 + e]], 1);
}

__global__ __launch_bounds__(256) void k_scanA(int N) {
    __shared__ int sh[256];
    int t = threadIdx.x;
    int i = blockIdx.x * 256 + t;
    sh[t] = (i < N) ? g_deg[i] : 0;
    __syncthreads();
    for (int off = 128; off > 0; off >>= 1) {
        if (t < off) sh[t] += sh[t + off];
        __syncthreads();
    }
    if (t == 0) g_blksum[blockIdx.x] = sh[0];
}

__global__ __launch_bounds__(256) void k_scanB(int NB) {
    __shared__ int sh[256];
    int t = threadIdx.x;
    sh[t] = (t < NB) ? g_blksum[t] : 0;
    __syncthreads();
    for (int off = 1; off < 256; off <<= 1) {
        int v = (t >= off) ? sh[t - off] : 0;
        __syncthreads();
        sh[t] += v;
        __syncthreads();
    }
    if (t < NB) g_blkoff[t] = (t == 0) ? 0 : sh[t - 1];
}

__global__ __launch_bounds__(256) void k_scanC(int N) {
    __shared__ int sh[256];
    int t = threadIdx.x;
    int i = blockIdx.x * 256 + t;
    int d = (i < N) ? g_deg[i] : 0;
    sh[t] = d;
    __syncthreads();
    for (int off = 1; off < 256; off <<= 1) {
        int v = (t >= off) ? sh[t - off] : 0;
        __syncthreads();
        sh[t] += v;
        __syncthreads();
    }
    if (i < N) {
        int ex = sh[t] - d + g_blkoff[blockIdx.x];
        g_off[i] = ex;
        g_pos[i] = ex;
    }
}

__global__ void k_fill(const int* __restrict__ ei, int E0) {
    int e = blockIdx.x * blockDim.x + threadIdx.x;
    if (e >= E0) return;
    int s = ei[e], d = ei[E0 + e];
    int idx = atomicAdd(&g_pos[d], 1);
    g_srcs[idx] = s;
}

// ---------------- tf32 GEMM + fused att-logit epilogue; h stored fp16 -------
#define ASTR 36
#define BSTR 136
#define A_ELEMS (128 * ASTR)
#define B_ELEMS (32 * BSTR)
#define ATT_OFF (2 * A_ELEMS + 2 * B_ELEMS)

__global__ __launch_bounds__(256, 2) void k_gemm(
    const float* __restrict__ A, const float* __restrict__ B,
    const float* __restrict__ attSrc, const float* __restrict__ attDst, int M)
{
    extern __shared__ float smem[];
    const int bm = blockIdx.y * 128;
    const int bn = blockIdx.x * 128;
    const int tid = threadIdx.x;
    const int wid = tid >> 5, lane = tid & 31;
    const int wm = (wid & 3) * 32;
    const int wn = (wid >> 2) * 64;
    const int g = lane >> 2, t = lane & 3;

    const int ar = tid >> 3, ac = (tid & 7) * 4;
    const int br = tid >> 6, bc = (tid & 63) * 2;

    if (tid < 128)      smem[ATT_OFF + tid] = attSrc[bn + tid];
    else                smem[ATT_OFF + 128 + (tid - 128)] = attDst[bn + tid - 128];

    float acc[2][8][4];
    #pragma unroll
    for (int mi = 0; mi < 2; mi++)
        #pragma unroll
        for (int ni = 0; ni < 8; ni++)
            #pragma unroll
            for (int q = 0; q < 4; q++) acc[mi][ni][q] = 0.f;

    float4 ra[4];
    float2 rb[8];

    auto ldg_tile = [&](int k0) {
        #pragma unroll
        for (int p = 0; p < 4; p++) {
            int r = ar + p * 32;
            ra[p] = make_float4(0.f, 0.f, 0.f, 0.f);
            if (bm + r < M) ra[p] = *(const float4*)&A[(long)(bm + r) * F + k0 + ac];
        }
        #pragma unroll
        for (int p = 0; p < 8; p++) {
            int r = br + p * 4;
            rb[p] = *(const float2*)&B[(long)(k0 + r) * F + bn + bc];
        }
    };
    auto sts_tile = [&](int st) {
        float* As = smem + st * A_ELEMS;
        float* Bs = smem + 2 * A_ELEMS + st * B_ELEMS;
        #pragma unroll
        for (int p = 0; p < 4; p++) {
            float4 w;
            w.x = __uint_as_float(f2tf32(ra[p].x)); w.y = __uint_as_float(f2tf32(ra[p].y));
            w.z = __uint_as_float(f2tf32(ra[p].z)); w.w = __uint_as_float(f2tf32(ra[p].w));
            *(float4*)&As[(ar + p * 32) * ASTR + ac] = w;
        }
        #pragma unroll
        for (int p = 0; p < 8; p++) {
            float2 w;
            w.x = __uint_as_float(f2tf32(rb[p].x)); w.y = __uint_as_float(f2tf32(rb[p].y));
            *(float2*)&Bs[(br + p * 4) * BSTR + bc] = w;
        }
    };
    auto compute = [&](int st) {
        float* As = smem + st * A_ELEMS;
        float* Bs = smem + 2 * A_ELEMS + st * B_ELEMS;
        #pragma unroll
        for (int kk = 0; kk < 4; kk++) {
            const int k = kk * 8;
            unsigned a[2][4], b[8][2];
            #pragma unroll
            for (int mi = 0; mi < 2; mi++) {
                int rb0 = wm + mi * 16;
                a[mi][0] = __float_as_uint(As[(rb0 + g) * ASTR + k + t]);
                a[mi][1] = __float_as_uint(As[(rb0 + g + 8) * ASTR + k + t]);
                a[mi][2] = __float_as_uint(As[(rb0 + g) * ASTR + k + t + 4]);
                a[mi][3] = __float_as_uint(As[(rb0 + g + 8) * ASTR + k + t + 4]);
            }
            #pragma unroll
            for (int ni = 0; ni < 8; ni++) {
                int col = wn + ni * 8 + g;
                b[ni][0] = __float_as_uint(Bs[(k + t) * BSTR + col]);
                b[ni][1] = __float_as_uint(Bs[(k + t + 4) * BSTR + col]);
            }
            #pragma unroll
            for (int mi = 0; mi < 2; mi++)
                #pragma unroll
                for (int ni = 0; ni < 8; ni++) {
                    asm volatile(
                        "mma.sync.aligned.m16n8k8.row.col.f32.tf32.tf32.f32 "
                        "{%0,%1,%2,%3}, {%4,%5,%6,%7}, {%8,%9}, {%0,%1,%2,%3};"
                        : "+f"(acc[mi][ni][0]), "+f"(acc[mi][ni][1]),
                          "+f"(acc[mi][ni][2]), "+f"(acc[mi][ni][3])
                        : "r"(a[mi][0]), "r"(a[mi][1]), "r"(a[mi][2]), "r"(a[mi][3]),
                          "r"(b[ni][0]), "r"(b[ni][1]));
                }
        }
    };

    ldg_tile(0);
    sts_tile(0);
    __syncthreads();
    #pragma unroll
    for (int kt = 1; kt < 8; kt++) {
        ldg_tile(kt * 32);
        compute((kt - 1) & 1);
        sts_tile(kt & 1);
        __syncthreads();
    }
    compute(1);

    // store h as fp16 (half2 per register pair)
    #pragma unroll
    for (int mi = 0; mi < 2; mi++) {
        #pragma unroll
        for (int ni = 0; ni < 8; ni++) {
            int col = bn + wn + ni * 8 + t * 2;
            int r0 = bm + wm + mi * 16 + g;
            int r1 = r0 + 8;
            if (r0 < M) *(__half2*)&g_hh[(long)r0 * F + col] = __floats2half2_rn(acc[mi][ni][0], acc[mi][ni][1]);
            if (r1 < M) *(__half2*)&g_hh[(long)r1 * F + col] = __floats2half2_rn(acc[mi][ni][2], acc[mi][ni][3]);
        }
    }

    // fused attention-logit epilogue (fp32 accumulators)
    const float* attS = smem + ATT_OFF;
    const float* attD = smem + ATT_OFF + 128;
    const int hbA = (bn + wn) >> 5;
    #pragma unroll
    for (int mi = 0; mi < 2; mi++) {
        #pragma unroll
        for (int rr = 0; rr < 2; rr++) {
            int row = bm + wm + mi * 16 + g + rr * 8;
            float sA = 0.f, dA = 0.f, sB = 0.f, dB = 0.f;
            #pragma unroll
            for (int ni = 0; ni < 8; ni++) {
                #pragma unroll
                for (int q = 0; q < 2; q++) {
                    int col = wn + ni * 8 + t * 2 + q;
                    float a = acc[mi][ni][rr * 2 + q];
                    if (ni < 4) { sA = fmaf(a, attS[col], sA); dA = fmaf(a, attD[col], dA); }
                    else        { sB = fmaf(a, attS[col], sB); dB = fmaf(a, attD[col], dB); }
                }
            }
            sA += __shfl_xor_sync(0xffffffffu, sA, 1); sA += __shfl_xor_sync(0xffffffffu, sA, 2);
            dA += __shfl_xor_sync(0xffffffffu, dA, 1); dA += __shfl_xor_sync(0xffffffffu, dA, 2);
            sB += __shfl_xor_sync(0xffffffffu, sB, 1); sB += __shfl_xor_sync(0xffffffffu, sB, 2);
            dB += __shfl_xor_sync(0xffffffffu, dB, 1); dB += __shfl_xor_sync(0xffffffffu, dB, 2);
            if (t == 0 && row < M) {
                g_asrc[row * 8 + hbA]     = sA;
                g_adst[row * 8 + hbA]     = dA;
                g_asrc[row * 8 + hbA + 1] = sB;
                g_adst[row * 8 + hbA + 1] = dB;
            }
        }
    }
}

// ---------------- fused aggregate: one WARP per dst node, fp16 gathers ------
// lane owns channels [lane*4,+4) (head lane>>3) and [128+lane*4,+4) (head 4+..)
// per edge: 2x LDG.64 (uint2 of half2) + 2 shfl + 8 FMA; fp32 accumulation
__global__ __launch_bounds__(256) void k_agg(const float* __restrict__ bias,
                                             float* __restrict__ out, int N) {
    int n = (blockIdx.x * blockDim.x + threadIdx.x) >> 5;
    int lane = threadIdx.x & 31;
    if (n >= N) return;
    const int hsel = lane >> 3;

    float adst_l = 0.f, aself_l = 0.f;
    if (lane < 8) {
        adst_l  = g_adst[n * 8 + lane];
        aself_l = g_asrc[n * 8 + lane];
    }
    float a0 = aself_l + adst_l;
    float ex_l = expf(a0 > 0.f ? a0 : 0.2f * a0);
    float eA = __shfl_sync(0xffffffffu, ex_l, hsel);
    float eB = __shfl_sync(0xffffffffu, ex_l, 4 + hsel);

    const __half2* hn = (const __half2*)&g_hh[(long)n * F];
    __half2 sA0 = hn[lane * 2], sA1 = hn[lane * 2 + 1];
    __half2 sB0 = hn[64 + lane * 2], sB1 = hn[64 + lane * 2 + 1];
    float2 fA0 = __half22float2(sA0), fA1 = __half22float2(sA1);
    float2 fB0 = __half22float2(sB0), fB1 = __half22float2(sB1);

    float denA = eA, denB = eB;
    float4 accA = make_float4(eA * fA0.x, eA * fA0.y, eA * fA1.x, eA * fA1.y);
    float4 accB = make_float4(eB * fB0.x, eB * fB0.y, eB * fB1.x, eB * fB1.y);

    int deg  = g_deg[n];
    int base = g_off[n];
    #pragma unroll 4
    for (int i = 0; i < deg; i++) {
        int s = g_srcs[base + i];
        float asl = (lane < 8) ? g_asrc[s * 8 + lane] : 0.f;
        float aa = asl + adst_l;
        float el = expf(aa > 0.f ? aa : 0.2f * aa);
        float e1 = __shfl_sync(0xffffffffu, el, hsel);
        float e2 = __shfl_sync(0xffffffffu, el, 4 + hsel);
        const __half2* hs = (const __half2*)&g_hh[(long)s * F];
        // two 8-byte gathers: channels [lane*4,+4) and [128+lane*4,+4)
        uint2 wa = *(const uint2*)&hs[lane * 2];
        uint2 wb = *(const uint2*)&hs[64 + lane * 2];
        float2 a0f = __half22float2(*(__half2*)&wa.x);
        float2 a1f = __half22float2(*(__half2*)&wa.y);
        float2 b0f = __half22float2(*(__half2*)&wb.x);
        float2 b1f = __half22float2(*(__half2*)&wb.y);
        accA.x = fmaf(e1, a0f.x, accA.x); accA.y = fmaf(e1, a0f.y, accA.y);
        accA.z = fmaf(e1, a1f.x, accA.z); accA.w = fmaf(e1, a1f.y, accA.w);
        accB.x = fmaf(e2, b0f.x, accB.x); accB.y = fmaf(e2, b0f.y, accB.y);
        accB.z = fmaf(e2, b1f.x, accB.z); accB.w = fmaf(e2, b1f.y, accB.w);
        denA += e1; denB += e2;
    }

    float rA = 1.0f / (denA + 1e-16f);
    float rB = 1.0f / (denB + 1e-16f);
    const float4* b4 = (const float4*)bias;
    float4 bA = b4[lane], bB = b4[32 + lane];
    float4 oA, oB;
    oA.x = accA.x * rA + bA.x; oA.y = accA.y * rA + bA.y;
    oA.z = accA.z * rA + bA.z; oA.w = accA.w * rA + bA.w;
    oB.x = accB.x * rB + bB.x; oB.y = accB.y * rB + bB.y;
    oB.z = accB.z * rB + bB.z; oB.w = accB.w * rB + bB.w;
    oA.x = oA.x > 0.f ? oA.x : expm1f(oA.x);
    oA.y = oA.y > 0.f ? oA.y : expm1f(oA.y);
    oA.z = oA.z > 0.f ? oA.z : expm1f(oA.z);
    oA.w = oA.w > 0.f ? oA.w : expm1f(oA.w);
    oB.x = oB.x > 0.f ? oB.x : expm1f(oB.x);
    oB.y = oB.y > 0.f ? oB.y : expm1f(oB.y);
    oB.z = oB.z > 0.f ? oB.z : expm1f(oB.z);
    oB.w = oB.w > 0.f ? oB.w : expm1f(oB.w);
    float4* o4 = (float4*)&out[(long)n * F];
    o4[lane]      = oA;
    o4[32 + lane] = oB;
}

// ---------------- launch ----------------
extern "C" void kernel_launch(void* const* d_in, const int* in_sizes, int n_in,
                              void* d_out, int out_size) {
    const float* x    = (const float*)d_in[0];
    const int*   ei   = (const int*)d_in[1];
    const float* W    = (const float*)d_in[2];
    const float* asv  = (const float*)d_in[3];
    const float* adv  = (const float*)d_in[4];
    const float* bias = (const float*)d_in[5];
    float* out = (float*)d_out;

    const int N  = in_sizes[0] / F;          // 50000
    const int E0 = in_sizes[1] / 2;          // 800000
    const int NB = (N + 255) / 256;          // 196

    static cudaStream_t s_side = nullptr;
    static cudaEvent_t ev_fork = nullptr, ev_join = nullptr;
    if (s_side == nullptr) {
        cudaStreamCreateWithFlags(&s_side, cudaStreamNonBlocking);
        cudaEventCreateWithFlags(&ev_fork, cudaEventDisableTiming);
        cudaEventCreateWithFlags(&ev_join, cudaEventDisableTiming);
    }

    const int smem_bytes = (ATT_OFF + 256) * (int)sizeof(float);
    cudaFuncSetAttribute(k_gemm, cudaFuncAttributeMaxDynamicSharedMemorySize, smem_bytes);

    // fork: CSR build on side stream, GEMM on main stream (independent)
    cudaEventRecord(ev_fork, 0);
    cudaStreamWaitEvent(s_side, ev_fork, 0);

    k_init <<<NB, 256, 0, s_side>>>(N);
    k_count<<<(E0 + 255) / 256, 256, 0, s_side>>>(ei, E0);
    k_scanA<<<NB, 256, 0, s_side>>>(N);
    {
        dim3 grid(F / 128, (N + 127) / 128);
        k_gemm<<<grid, 256, smem_bytes>>>(x, W, asv, adv, N);   // profiled slot
    }
    k_scanB<<<1, 256, 0, s_side>>>(NB);
    k_scanC<<<NB, 256, 0, s_side>>>(N);
    k_fill <<<(E0 + 255) / 256, 256, 0, s_side>>>(ei, E0);

    // join: aggregation needs both branches
    cudaEventRecord(ev_join, s_side);
    cudaStreamWaitEvent(0, ev_join, 0);
    {
        int blocks = (N + 7) / 8;
        k_agg<<<blocks, 256>>>(bias, out, N);
    }
}